// round 5
// baseline (speedup 1.0000x reference)
#include <cuda_runtime.h>
#include <cuda_fp16.h>
#include <cstdint>

// Shapes: X [8192,4096] fp32, W [4096,4096], b[4096], out [8192,4096] fp32.
static const int MTOT = 8192;
static const int NTOT = 4096;
static const int KTOT = 4096;

// GEMM tiling
#define BM 128
#define BN 256
#define BK 128
#define SSTAGE 98304        // Xh 32K (2 subtiles) + Wh 64K (2 subtiles)
#define NSTAGES 2
#define NCHUNK (KTOT / BK)  // 32

// Scratch (__device__ globals; allocation-free rule)
__device__ __align__(1024) __half g_Xh[(size_t)MTOT * KTOT];
__device__ __align__(1024) __half g_Wh[(size_t)NTOT * KTOT];

// ---------------------------------------------------------------------------
// Kernel 1: convert X to fp16
// ---------------------------------------------------------------------------
__global__ void split_x_kernel(const float4* __restrict__ x, int n4) {
    int i = blockIdx.x * blockDim.x + threadIdx.x;
    if (i >= n4) return;
    float4 v = x[i];
    ushort4 hh;
    hh.x = __half_as_ushort(__float2half_rn(v.x));
    hh.y = __half_as_ushort(__float2half_rn(v.y));
    hh.z = __half_as_ushort(__float2half_rn(v.z));
    hh.w = __half_as_ushort(__float2half_rn(v.w));
    reinterpret_cast<ushort4*>(g_Xh)[i] = hh;
}

// ---------------------------------------------------------------------------
// Kernel 2: W_eff = W + B_u A_u + B_s A_s  ->  fp16
//   delta_s[n,k] = sum_t B0[n%2048, t] * A0[(t + n/2048 - k/2048) mod 56, k%2048]
// ---------------------------------------------------------------------------
__global__ void build_w_kernel(const float* __restrict__ W,
                               const float* __restrict__ A_u,
                               const float* __restrict__ B_u,
                               const float* __restrict__ A0,
                               const float* __restrict__ B0) {
    __shared__ float sAu[8][128];
    __shared__ float sA0[56][128];
    __shared__ float sBu[32][8];
    __shared__ float sB0[32][56];

    int tid = threadIdx.x;                 // 0..127
    int k = blockIdx.x * 128 + tid;
    int i = k >> 11;
    int kk = k & 2047;
    int nbase = blockIdx.y * 32;
    int j = nbase >> 11;
    int nb2 = nbase & 2047;

#pragma unroll
    for (int u = 0; u < 8; u++) sAu[u][tid] = A_u[u * 4096 + k];
#pragma unroll
    for (int r = 0; r < 56; r++) sA0[r][tid] = A0[r * 2048 + kk];
    for (int idx = tid; idx < 32 * 8; idx += 128) {
        int ln = idx >> 3, u = idx & 7;
        sBu[ln][u] = B_u[(nbase + ln) * 8 + u];
    }
    for (int idx = tid; idx < 32 * 56; idx += 128) {
        int ln = idx / 56, t = idx % 56;
        sB0[ln][t] = B0[(nb2 + ln) * 56 + t];
    }
    __syncthreads();

    int d = j - i;  // -1, 0, or 1
    for (int ln = 0; ln < 32; ln++) {
        int n = nbase + ln;
        float acc = W[(size_t)n * 4096 + k];
#pragma unroll
        for (int u = 0; u < 8; u++) acc += sBu[ln][u] * sAu[u][tid];
#pragma unroll
        for (int t = 0; t < 56; t++) {
            int rr = t + d;
            rr = (rr >= 56) ? rr - 56 : (rr < 0 ? rr + 56 : rr);
            acc += sB0[ln][t] * sA0[rr][tid];
        }
        g_Wh[(size_t)n * 4096 + k] = __float2half_rn(acc);
    }
}

// ---------------------------------------------------------------------------
// Kernel 3: GEMM  out = Xh * Wh^T + b   (fp16 inputs, fp32 accum)
// CTA 128x256xBK128, 512 threads (16 warps, 4x4), warp tile 32x64,
// 2-stage cp.async pipeline, register double-buffered fragments.
// Stage layout: [Xsub0 16K][Xsub1 16K][Wsub0 32K][Wsub1 32K], each subtile
// is the proven BK=64 swizzled layout (128B rows, 16B-chunk XOR swizzle).
// ---------------------------------------------------------------------------
__device__ __forceinline__ void cp16(uint32_t dst, const void* src) {
    asm volatile("cp.async.cg.shared.global [%0], [%1], 16;" :: "r"(dst), "l"(src));
}
__device__ __forceinline__ void ldsm4(uint32_t& r0, uint32_t& r1, uint32_t& r2,
                                      uint32_t& r3, uint32_t addr) {
    asm volatile("ldmatrix.sync.aligned.m8n8.x4.shared.b16 {%0,%1,%2,%3}, [%4];"
                 : "=r"(r0), "=r"(r1), "=r"(r2), "=r"(r3) : "r"(addr));
}
__device__ __forceinline__ void mma16816(float* c, const uint32_t* a,
                                         uint32_t b0, uint32_t b1) {
    asm volatile(
        "mma.sync.aligned.m16n8k16.row.col.f32.f16.f16.f32 "
        "{%0,%1,%2,%3},{%4,%5,%6,%7},{%8,%9},{%0,%1,%2,%3};"
        : "+f"(c[0]), "+f"(c[1]), "+f"(c[2]), "+f"(c[3])
        : "r"(a[0]), "r"(a[1]), "r"(a[2]), "r"(a[3]), "r"(b0), "r"(b1));
}

__global__ void __launch_bounds__(512, 1)
gemm_kernel(const float* __restrict__ bias, float* __restrict__ out) {
    extern __shared__ char smem[];
    uint32_t sbase = (uint32_t)__cvta_generic_to_shared(smem);
    int tid = threadIdx.x;
    int lane = tid & 31, warp = tid >> 5;
    int wm = warp >> 2;   // 0..3 : 32 rows each
    int wn = warp & 3;    // 0..3 : 64 cols each
    int bm = blockIdx.y, bn = blockIdx.x;

    const __half* gXh = g_Xh + (size_t)bm * BM * 4096;
    const __half* gWh = g_Wh + (size_t)bn * BN * 4096;

    // Load one BK=128 stage = 2 BK=64 subtiles per array.
    auto load_stage = [&](int s, int kt) {
        uint32_t st = sbase + s * SSTAGE;
#pragma unroll
        for (int kk = 0; kk < 2; kk++) {
            // X subtile: 128 rows x 8 chunks = 1024 ops (2/thread)
#pragma unroll
            for (int i2 = 0; i2 < 2; i2++) {
                int idx = tid + i2 * 512;
                int r = idx >> 3, c = idx & 7;
                uint32_t dst = st + kk * 16384 + r * 128 + ((c ^ (r & 7)) << 4);
                cp16(dst, gXh + (size_t)r * 4096 + kt * BK + kk * 64 + c * 8);
            }
            // W subtile: 256 rows x 8 chunks = 2048 ops (4/thread)
#pragma unroll
            for (int i2 = 0; i2 < 4; i2++) {
                int idx = tid + i2 * 512;
                int r = idx >> 3, c = idx & 7;
                uint32_t dst = st + 32768 + kk * 32768 + r * 128 +
                               ((c ^ (r & 7)) << 4);
                cp16(dst, gWh + (size_t)r * 4096 + kt * BK + kk * 64 + c * 8);
            }
        }
    };

    float acc[2][8][4];
#pragma unroll
    for (int a = 0; a < 2; a++)
#pragma unroll
        for (int b = 0; b < 8; b++)
#pragma unroll
            for (int c = 0; c < 4; c++) acc[a][b][c] = 0.0f;

    load_stage(0, 0);
    asm volatile("cp.async.commit_group;");

    int arow = wm * 32 + (lane & 15);
    int nrow0 = wn * 64 + (lane & 7) + ((lane >> 4) << 3);

    uint32_t ah[2][2][4];   // [buf][mt][frag]
    uint32_t bh[2][4][4];   // [buf][q][frag]

    for (int kt = 0; kt < NCHUNK; kt++) {
        uint32_t st = sbase + (kt & 1) * SSTAGE;

        // Issue next chunk's loads into the other stage (freed by the barrier
        // at the end of the previous iteration), then wait for this chunk.
        if (kt + 1 < NCHUNK) {
            load_stage((kt + 1) & 1, kt + 1);
            asm volatile("cp.async.commit_group;");
            asm volatile("cp.async.wait_group 1;");
        } else {
            asm volatile("cp.async.wait_group 0;");
        }
        __syncthreads();

        auto lda = [&](int buf, int ks) {
            int kk = ks >> 2, ksub = ks & 3;
            uint32_t base = st + kk * 16384;
            int ach = ksub * 2 + (lane >> 4);
#pragma unroll
            for (int mt = 0; mt < 2; mt++) {
                int row = arow + mt * 16;
                uint32_t off = row * 128 + ((ach ^ (row & 7)) << 4);
                ldsm4(ah[buf][mt][0], ah[buf][mt][1], ah[buf][mt][2],
                      ah[buf][mt][3], base + off);
            }
        };
        auto ldb = [&](int buf, int ks) {
            int kk = ks >> 2, ksub = ks & 3;
            uint32_t base = st + 32768 + kk * 32768;
            int bch = ksub * 2 + ((lane >> 3) & 1);
#pragma unroll
            for (int q = 0; q < 4; q++) {
                int row = nrow0 + q * 16;
                uint32_t off = row * 128 + ((bch ^ (row & 7)) << 4);
                ldsm4(bh[buf][q][0], bh[buf][q][1], bh[buf][q][2],
                      bh[buf][q][3], base + off);
            }
        };

        lda(0, 0);
        ldb(0, 0);
#pragma unroll
        for (int ks = 0; ks < 8; ks++) {
            int cur = ks & 1, nxt = cur ^ 1;
            if (ks < 7) {
                lda(nxt, ks + 1);
                ldb(nxt, ks + 1);
            }
#pragma unroll
            for (int mt = 0; mt < 2; mt++) {
#pragma unroll
                for (int nt = 0; nt < 8; nt++) {
                    int q = nt >> 1, o = (nt & 1) * 2;
                    mma16816(acc[mt][nt], ah[cur][mt], bh[cur][q][o],
                             bh[cur][q][o + 1]);
                }
            }
        }
        __syncthreads();  // all reads of this stage done before it is refilled
    }

    // Epilogue: add bias, write fp32 directly
    const float* bptr = bias + bn * BN + wn * 64;
    size_t outbase = (size_t)(bm * BM + wm * 32) * 4096 + bn * BN + wn * 64;
    int gid = lane >> 2, tig = lane & 3;
#pragma unroll
    for (int nt = 0; nt < 8; nt++) {
        int c = nt * 8 + tig * 2;
        float b0 = bptr[c], b1 = bptr[c + 1];
#pragma unroll
        for (int mt = 0; mt < 2; mt++) {
            int r = mt * 16 + gid;
            float2 v0 = make_float2(acc[mt][nt][0] + b0, acc[mt][nt][1] + b1);
            float2 v1 = make_float2(acc[mt][nt][2] + b0, acc[mt][nt][3] + b1);
            *reinterpret_cast<float2*>(out + outbase + (size_t)r * 4096 + c) = v0;
            *reinterpret_cast<float2*>(out + outbase + (size_t)(r + 8) * 4096 + c) = v1;
        }
    }
}

// ---------------------------------------------------------------------------
extern "C" void kernel_launch(void* const* d_in, const int* in_sizes, int n_in,
                              void* d_out, int out_size) {
    const float* x  = (const float*)d_in[0];
    const float* W  = (const float*)d_in[1];
    const float* b  = (const float*)d_in[2];
    const float* Au = (const float*)d_in[3];
    const float* Bu = (const float*)d_in[4];
    const float* A0 = (const float*)d_in[5];
    const float* B0 = (const float*)d_in[6];
    float* out = (float*)d_out;

    int n4 = (MTOT * KTOT) / 4;
    split_x_kernel<<<(n4 + 255) / 256, 256>>>((const float4*)x, n4);
    build_w_kernel<<<dim3(KTOT / 128, NTOT / 32), 128>>>(W, Au, Bu, A0, B0);

    cudaFuncSetAttribute(gemm_kernel,
                         cudaFuncAttributeMaxDynamicSharedMemorySize,
                         NSTAGES * SSTAGE);
    gemm_kernel<<<dim3(NTOT / BN, MTOT / BM), 512, NSTAGES * SSTAGE>>>(b, out);
}

// round 6
// speedup vs baseline: 1.0122x; 1.0122x over previous
#include <cuda_runtime.h>
#include <cuda_fp16.h>
#include <cstdint>

// Shapes: X [8192,4096] fp32, W [4096,4096], b[4096], out [8192,4096] fp32.
static const int MTOT = 8192;
static const int NTOT = 4096;
static const int KTOT = 4096;

// GEMM tiling: CTA 128x128xBK64, 256 threads, 2 CTAs/SM.
#define BM 128
#define BN 128
#define BK 64
#define SSTAGE 32768        // Xh 16K + Wh 16K
#define NSTAGES 3
#define NCHUNK (KTOT / BK)  // 64

// Scratch (__device__ globals; allocation-free rule)
__device__ __align__(1024) __half g_Xh[(size_t)MTOT * KTOT];
__device__ __align__(1024) __half g_Wh[(size_t)NTOT * KTOT];

// ---------------------------------------------------------------------------
// Kernel 1: convert X to fp16
// ---------------------------------------------------------------------------
__global__ void split_x_kernel(const float4* __restrict__ x, int n4) {
    int i = blockIdx.x * blockDim.x + threadIdx.x;
    if (i >= n4) return;
    float4 v = x[i];
    ushort4 hh;
    hh.x = __half_as_ushort(__float2half_rn(v.x));
    hh.y = __half_as_ushort(__float2half_rn(v.y));
    hh.z = __half_as_ushort(__float2half_rn(v.z));
    hh.w = __half_as_ushort(__float2half_rn(v.w));
    reinterpret_cast<ushort4*>(g_Xh)[i] = hh;
}

// ---------------------------------------------------------------------------
// Kernel 2: W_eff = W + B_u A_u + B_s A_s  ->  fp16
//   delta_s[n,k] = sum_t B0[n%2048, t] * A0[(t + n/2048 - k/2048) mod 56, k%2048]
// ---------------------------------------------------------------------------
__global__ void build_w_kernel(const float* __restrict__ W,
                               const float* __restrict__ A_u,
                               const float* __restrict__ B_u,
                               const float* __restrict__ A0,
                               const float* __restrict__ B0) {
    __shared__ float sAu[8][128];
    __shared__ float sA0[56][128];
    __shared__ float sBu[32][8];
    __shared__ float sB0[32][56];

    int tid = threadIdx.x;                 // 0..127
    int k = blockIdx.x * 128 + tid;
    int i = k >> 11;
    int kk = k & 2047;
    int nbase = blockIdx.y * 32;
    int j = nbase >> 11;
    int nb2 = nbase & 2047;

#pragma unroll
    for (int u = 0; u < 8; u++) sAu[u][tid] = A_u[u * 4096 + k];
#pragma unroll
    for (int r = 0; r < 56; r++) sA0[r][tid] = A0[r * 2048 + kk];
    for (int idx = tid; idx < 32 * 8; idx += 128) {
        int ln = idx >> 3, u = idx & 7;
        sBu[ln][u] = B_u[(nbase + ln) * 8 + u];
    }
    for (int idx = tid; idx < 32 * 56; idx += 128) {
        int ln = idx / 56, t = idx % 56;
        sB0[ln][t] = B0[(nb2 + ln) * 56 + t];
    }
    __syncthreads();

    int d = j - i;  // -1, 0, or 1
    for (int ln = 0; ln < 32; ln++) {
        int n = nbase + ln;
        float acc = W[(size_t)n * 4096 + k];
#pragma unroll
        for (int u = 0; u < 8; u++) acc += sBu[ln][u] * sAu[u][tid];
#pragma unroll
        for (int t = 0; t < 56; t++) {
            int rr = t + d;
            rr = (rr >= 56) ? rr - 56 : (rr < 0 ? rr + 56 : rr);
            acc += sB0[ln][t] * sA0[rr][tid];
        }
        g_Wh[(size_t)n * 4096 + k] = __float2half_rn(acc);
    }
}

// ---------------------------------------------------------------------------
// Kernel 3: GEMM  out = Xh * Wh^T + b   (fp16 inputs, fp32 accum)
// CTA 128x128xBK64, 256 threads (8 warps, 2x4), warp tile 64x32,
// 3-stage cp.async pipeline, 2 CTAs/SM for cross-CTA latency hiding.
// ---------------------------------------------------------------------------
__device__ __forceinline__ void cp16(uint32_t dst, const void* src) {
    asm volatile("cp.async.cg.shared.global [%0], [%1], 16;" :: "r"(dst), "l"(src));
}
__device__ __forceinline__ void ldsm4(uint32_t& r0, uint32_t& r1, uint32_t& r2,
                                      uint32_t& r3, uint32_t addr) {
    asm volatile("ldmatrix.sync.aligned.m8n8.x4.shared.b16 {%0,%1,%2,%3}, [%4];"
                 : "=r"(r0), "=r"(r1), "=r"(r2), "=r"(r3) : "r"(addr));
}
__device__ __forceinline__ void mma16816(float* c, const uint32_t* a,
                                         uint32_t b0, uint32_t b1) {
    asm volatile(
        "mma.sync.aligned.m16n8k16.row.col.f32.f16.f16.f32 "
        "{%0,%1,%2,%3},{%4,%5,%6,%7},{%8,%9},{%0,%1,%2,%3};"
        : "+f"(c[0]), "+f"(c[1]), "+f"(c[2]), "+f"(c[3])
        : "r"(a[0]), "r"(a[1]), "r"(a[2]), "r"(a[3]), "r"(b0), "r"(b1));
}

__global__ void __launch_bounds__(256, 2)
gemm_kernel(const float* __restrict__ bias, float* __restrict__ out) {
    extern __shared__ char smem[];
    uint32_t sbase = (uint32_t)__cvta_generic_to_shared(smem);
    int tid = threadIdx.x;
    int lane = tid & 31, warp = tid >> 5;
    int wm = warp >> 2;   // 0..1 : 64 rows each
    int wn = warp & 3;    // 0..3 : 32 cols each
    int bm = blockIdx.y, bn = blockIdx.x;

    const __half* gXh = g_Xh + (size_t)bm * BM * 4096;
    const __half* gWh = g_Wh + (size_t)bn * BN * 4096;

    auto load_stage = [&](int s, int kt) {
        uint32_t st = sbase + s * SSTAGE;
        // Xh: 128 rows x 8 chunks = 1024 ops (4/thread)
#pragma unroll
        for (int i2 = 0; i2 < 4; i2++) {
            int idx = tid + i2 * 256;
            int r = idx >> 3, c = idx & 7;
            uint32_t dst = st + r * 128 + ((c ^ (r & 7)) << 4);
            cp16(dst, gXh + (size_t)r * 4096 + kt * BK + c * 8);
        }
        // Wh: 128 rows x 8 chunks = 1024 ops (4/thread)
#pragma unroll
        for (int i2 = 0; i2 < 4; i2++) {
            int idx = tid + i2 * 256;
            int r = idx >> 3, c = idx & 7;
            uint32_t dst = st + 16384 + r * 128 + ((c ^ (r & 7)) << 4);
            cp16(dst, gWh + (size_t)r * 4096 + kt * BK + c * 8);
        }
    };

    float acc[4][4][4];
#pragma unroll
    for (int a = 0; a < 4; a++)
#pragma unroll
        for (int b = 0; b < 4; b++)
#pragma unroll
            for (int c = 0; c < 4; c++) acc[a][b][c] = 0.0f;

    load_stage(0, 0);
    asm volatile("cp.async.commit_group;");
    load_stage(1, 1);
    asm volatile("cp.async.commit_group;");

    int arow = wm * 64 + (lane & 15);
    int nrow0 = wn * 32 + (lane & 7) + ((lane >> 4) << 3);

    for (int kt = 0; kt < NCHUNK; kt++) {
        asm volatile("cp.async.wait_group 1;");
        __syncthreads();
        int ls = kt + 2;
        if (ls < NCHUNK) load_stage(ls % NSTAGES, ls);
        asm volatile("cp.async.commit_group;");

        uint32_t st = sbase + (kt % NSTAGES) * SSTAGE;
#pragma unroll
        for (int ks = 0; ks < 4; ks++) {
            uint32_t ah[4][4], bh[2][4];
            int ach = ks * 2 + (lane >> 4);
            int bch = ks * 2 + ((lane >> 3) & 1);
#pragma unroll
            for (int mt = 0; mt < 4; mt++) {
                int row = arow + mt * 16;
                uint32_t off = row * 128 + ((ach ^ (row & 7)) << 4);
                ldsm4(ah[mt][0], ah[mt][1], ah[mt][2], ah[mt][3], st + off);
            }
#pragma unroll
            for (int q = 0; q < 2; q++) {
                int row = nrow0 + q * 16;
                uint32_t off = row * 128 + ((bch ^ (row & 7)) << 4);
                ldsm4(bh[q][0], bh[q][1], bh[q][2], bh[q][3], st + 16384 + off);
            }
#pragma unroll
            for (int mt = 0; mt < 4; mt++) {
#pragma unroll
                for (int nt = 0; nt < 4; nt++) {
                    int q = nt >> 1, o = (nt & 1) * 2;
                    mma16816(acc[mt][nt], ah[mt], bh[q][o], bh[q][o + 1]);
                }
            }
        }
        __syncthreads();
    }

    // Epilogue: add bias, write fp32 directly
    const float* bptr = bias + bn * BN + wn * 32;
    size_t outbase = (size_t)(bm * BM + wm * 64) * 4096 + bn * BN + wn * 32;
    int gid = lane >> 2, tig = lane & 3;
#pragma unroll
    for (int nt = 0; nt < 4; nt++) {
        int c = nt * 8 + tig * 2;
        float b0 = bptr[c], b1 = bptr[c + 1];
#pragma unroll
        for (int mt = 0; mt < 4; mt++) {
            int r = mt * 16 + gid;
            float2 v0 = make_float2(acc[mt][nt][0] + b0, acc[mt][nt][1] + b1);
            float2 v1 = make_float2(acc[mt][nt][2] + b0, acc[mt][nt][3] + b1);
            *reinterpret_cast<float2*>(out + outbase + (size_t)r * 4096 + c) = v0;
            *reinterpret_cast<float2*>(out + outbase + (size_t)(r + 8) * 4096 + c) = v1;
        }
    }
}

// ---------------------------------------------------------------------------
extern "C" void kernel_launch(void* const* d_in, const int* in_sizes, int n_in,
                              void* d_out, int out_size) {
    const float* x  = (const float*)d_in[0];
    const float* W  = (const float*)d_in[1];
    const float* b  = (const float*)d_in[2];
    const float* Au = (const float*)d_in[3];
    const float* Bu = (const float*)d_in[4];
    const float* A0 = (const float*)d_in[5];
    const float* B0 = (const float*)d_in[6];
    float* out = (float*)d_out;

    int n4 = (MTOT * KTOT) / 4;
    split_x_kernel<<<(n4 + 255) / 256, 256>>>((const float4*)x, n4);
    build_w_kernel<<<dim3(KTOT / 128, NTOT / 32), 128>>>(W, Au, Bu, A0, B0);

    cudaFuncSetAttribute(gemm_kernel,
                         cudaFuncAttributeMaxDynamicSharedMemorySize,
                         NSTAGES * SSTAGE);
    gemm_kernel<<<dim3(NTOT / BN, MTOT / BM), 256, NSTAGES * SSTAGE>>>(b, out);
}

// round 7
// speedup vs baseline: 1.0740x; 1.0611x over previous
#include <cuda_runtime.h>
#include <cuda_fp16.h>
#include <cstdint>

// Shapes: X [8192,4096] fp32, W [4096,4096], b[4096], out [8192,4096] fp32.
static const int MTOT = 8192;
static const int NTOT = 4096;
static const int KTOT = 4096;

// GEMM tiling: CTA 128x128xBK64, 128 threads (4 warps, 2x2, 64x64 warp tile),
// 2 CTAs/SM.
#define BM 128
#define BN 128
#define BK 64
#define SSTAGE 32768        // Xh 16K + Wh 16K
#define NSTAGES 3
#define NCHUNK (KTOT / BK)  // 64

// Scratch (__device__ globals; allocation-free rule)
__device__ __align__(1024) __half g_Xh[(size_t)MTOT * KTOT];
__device__ __align__(1024) __half g_Wh[(size_t)NTOT * KTOT];

// ---------------------------------------------------------------------------
// Kernel 1: convert X to fp16
// ---------------------------------------------------------------------------
__global__ void split_x_kernel(const float4* __restrict__ x, int n4) {
    int i = blockIdx.x * blockDim.x + threadIdx.x;
    if (i >= n4) return;
    float4 v = x[i];
    ushort4 hh;
    hh.x = __half_as_ushort(__float2half_rn(v.x));
    hh.y = __half_as_ushort(__float2half_rn(v.y));
    hh.z = __half_as_ushort(__float2half_rn(v.z));
    hh.w = __half_as_ushort(__float2half_rn(v.w));
    reinterpret_cast<ushort4*>(g_Xh)[i] = hh;
}

// ---------------------------------------------------------------------------
// Kernel 2: W_eff = W + B_u A_u + B_s A_s  ->  fp16
//   delta_s[n,k] = sum_t B0[n%2048, t] * A0[(t + n/2048 - k/2048) mod 56, k%2048]
// ---------------------------------------------------------------------------
__global__ void build_w_kernel(const float* __restrict__ W,
                               const float* __restrict__ A_u,
                               const float* __restrict__ B_u,
                               const float* __restrict__ A0,
                               const float* __restrict__ B0) {
    __shared__ float sAu[8][128];
    __shared__ float sA0[56][128];
    __shared__ float sBu[32][8];
    __shared__ float sB0[32][56];

    int tid = threadIdx.x;                 // 0..127
    int k = blockIdx.x * 128 + tid;
    int i = k >> 11;
    int kk = k & 2047;
    int nbase = blockIdx.y * 32;
    int j = nbase >> 11;
    int nb2 = nbase & 2047;

#pragma unroll
    for (int u = 0; u < 8; u++) sAu[u][tid] = A_u[u * 4096 + k];
#pragma unroll
    for (int r = 0; r < 56; r++) sA0[r][tid] = A0[r * 2048 + kk];
    for (int idx = tid; idx < 32 * 8; idx += 128) {
        int ln = idx >> 3, u = idx & 7;
        sBu[ln][u] = B_u[(nbase + ln) * 8 + u];
    }
    for (int idx = tid; idx < 32 * 56; idx += 128) {
        int ln = idx / 56, t = idx % 56;
        sB0[ln][t] = B0[(nb2 + ln) * 56 + t];
    }
    __syncthreads();

    int d = j - i;  // -1, 0, or 1
    for (int ln = 0; ln < 32; ln++) {
        int n = nbase + ln;
        float acc = W[(size_t)n * 4096 + k];
#pragma unroll
        for (int u = 0; u < 8; u++) acc += sBu[ln][u] * sAu[u][tid];
#pragma unroll
        for (int t = 0; t < 56; t++) {
            int rr = t + d;
            rr = (rr >= 56) ? rr - 56 : (rr < 0 ? rr + 56 : rr);
            acc += sB0[ln][t] * sA0[rr][tid];
        }
        g_Wh[(size_t)n * 4096 + k] = __float2half_rn(acc);
    }
}

// ---------------------------------------------------------------------------
// Kernel 3: GEMM  out = Xh * Wh^T + b   (fp16 inputs, fp32 accum)
// CTA 128x128xBK64, 128 threads (4 warps, 2x2), warp tile 64x64,
// 3-stage cp.async pipeline, 2 CTAs/SM. MMA:LDSM ratio = 4.
// ---------------------------------------------------------------------------
__device__ __forceinline__ void cp16(uint32_t dst, const void* src) {
    asm volatile("cp.async.cg.shared.global [%0], [%1], 16;" :: "r"(dst), "l"(src));
}
__device__ __forceinline__ void ldsm4(uint32_t& r0, uint32_t& r1, uint32_t& r2,
                                      uint32_t& r3, uint32_t addr) {
    asm volatile("ldmatrix.sync.aligned.m8n8.x4.shared.b16 {%0,%1,%2,%3}, [%4];"
                 : "=r"(r0), "=r"(r1), "=r"(r2), "=r"(r3) : "r"(addr));
}
__device__ __forceinline__ void mma16816(float* c, const uint32_t* a,
                                         uint32_t b0, uint32_t b1) {
    asm volatile(
        "mma.sync.aligned.m16n8k16.row.col.f32.f16.f16.f32 "
        "{%0,%1,%2,%3},{%4,%5,%6,%7},{%8,%9},{%0,%1,%2,%3};"
        : "+f"(c[0]), "+f"(c[1]), "+f"(c[2]), "+f"(c[3])
        : "r"(a[0]), "r"(a[1]), "r"(a[2]), "r"(a[3]), "r"(b0), "r"(b1));
}

__global__ void __launch_bounds__(128, 2)
gemm_kernel(const float* __restrict__ bias, float* __restrict__ out) {
    extern __shared__ char smem[];
    uint32_t sbase = (uint32_t)__cvta_generic_to_shared(smem);
    int tid = threadIdx.x;
    int lane = tid & 31, warp = tid >> 5;
    int wm = warp >> 1;   // 0..1 : 64 rows each
    int wn = warp & 1;    // 0..1 : 64 cols each
    int bm = blockIdx.y, bn = blockIdx.x;

    const __half* gXh = g_Xh + (size_t)bm * BM * 4096;
    const __half* gWh = g_Wh + (size_t)bn * BN * 4096;

    auto load_stage = [&](int s, int kt) {
        uint32_t st = sbase + s * SSTAGE;
        // Xh: 128 rows x 8 chunks = 1024 ops (8/thread)
#pragma unroll
        for (int i2 = 0; i2 < 8; i2++) {
            int idx = tid + i2 * 128;
            int r = idx >> 3, c = idx & 7;
            uint32_t dst = st + r * 128 + ((c ^ (r & 7)) << 4);
            cp16(dst, gXh + (size_t)r * 4096 + kt * BK + c * 8);
        }
        // Wh: 128 rows x 8 chunks = 1024 ops (8/thread)
#pragma unroll
        for (int i2 = 0; i2 < 8; i2++) {
            int idx = tid + i2 * 128;
            int r = idx >> 3, c = idx & 7;
            uint32_t dst = st + 16384 + r * 128 + ((c ^ (r & 7)) << 4);
            cp16(dst, gWh + (size_t)r * 4096 + kt * BK + c * 8);
        }
    };

    float acc[4][8][4];
#pragma unroll
    for (int a = 0; a < 4; a++)
#pragma unroll
        for (int b = 0; b < 8; b++)
#pragma unroll
            for (int c = 0; c < 4; c++) acc[a][b][c] = 0.0f;

    load_stage(0, 0);
    asm volatile("cp.async.commit_group;");
    load_stage(1, 1);
    asm volatile("cp.async.commit_group;");

    int arow = wm * 64 + (lane & 15);
    int nrow0 = wn * 64 + (lane & 7) + ((lane >> 4) << 3);

    for (int kt = 0; kt < NCHUNK; kt++) {
        asm volatile("cp.async.wait_group 1;");
        __syncthreads();
        int ls = kt + 2;
        if (ls < NCHUNK) load_stage(ls % NSTAGES, ls);
        asm volatile("cp.async.commit_group;");

        uint32_t st = sbase + (kt % NSTAGES) * SSTAGE;
#pragma unroll
        for (int ks = 0; ks < 4; ks++) {
            uint32_t ah[4][4], bh[4][4];
            int ach = ks * 2 + (lane >> 4);
            int bch = ks * 2 + ((lane >> 3) & 1);
#pragma unroll
            for (int mt = 0; mt < 4; mt++) {
                int row = arow + mt * 16;
                uint32_t off = row * 128 + ((ach ^ (row & 7)) << 4);
                ldsm4(ah[mt][0], ah[mt][1], ah[mt][2], ah[mt][3], st + off);
            }
#pragma unroll
            for (int q = 0; q < 4; q++) {
                int row = nrow0 + q * 16;
                uint32_t off = row * 128 + ((bch ^ (row & 7)) << 4);
                ldsm4(bh[q][0], bh[q][1], bh[q][2], bh[q][3], st + 16384 + off);
            }
#pragma unroll
            for (int mt = 0; mt < 4; mt++) {
#pragma unroll
                for (int nt = 0; nt < 8; nt++) {
                    int q = nt >> 1, o = (nt & 1) * 2;
                    mma16816(acc[mt][nt], ah[mt], bh[q][o], bh[q][o + 1]);
                }
            }
        }
        __syncthreads();
    }

    // Epilogue: add bias, write fp32 directly
    const float* bptr = bias + bn * BN + wn * 64;
    size_t outbase = (size_t)(bm * BM + wm * 64) * 4096 + bn * BN + wn * 64;
    int gid = lane >> 2, tig = lane & 3;
#pragma unroll
    for (int nt = 0; nt < 8; nt++) {
        int c = nt * 8 + tig * 2;
        float b0 = bptr[c], b1 = bptr[c + 1];
#pragma unroll
        for (int mt = 0; mt < 4; mt++) {
            int r = mt * 16 + gid;
            float2 v0 = make_float2(acc[mt][nt][0] + b0, acc[mt][nt][1] + b1);
            float2 v1 = make_float2(acc[mt][nt][2] + b0, acc[mt][nt][3] + b1);
            *reinterpret_cast<float2*>(out + outbase + (size_t)r * 4096 + c) = v0;
            *reinterpret_cast<float2*>(out + outbase + (size_t)(r + 8) * 4096 + c) = v1;
        }
    }
}

// ---------------------------------------------------------------------------
extern "C" void kernel_launch(void* const* d_in, const int* in_sizes, int n_in,
                              void* d_out, int out_size) {
    const float* x  = (const float*)d_in[0];
    const float* W  = (const float*)d_in[1];
    const float* b  = (const float*)d_in[2];
    const float* Au = (const float*)d_in[3];
    const float* Bu = (const float*)d_in[4];
    const float* A0 = (const float*)d_in[5];
    const float* B0 = (const float*)d_in[6];
    float* out = (float*)d_out;

    int n4 = (MTOT * KTOT) / 4;
    split_x_kernel<<<(n4 + 255) / 256, 256>>>((const float4*)x, n4);
    build_w_kernel<<<dim3(KTOT / 128, NTOT / 32), 128>>>(W, Au, Bu, A0, B0);

    cudaFuncSetAttribute(gemm_kernel,
                         cudaFuncAttributeMaxDynamicSharedMemorySize,
                         NSTAGES * SSTAGE);
    gemm_kernel<<<dim3(NTOT / BN, MTOT / BM), 128, NSTAGES * SSTAGE>>>(b, out);
}